// round 17
// baseline (speedup 1.0000x reference)
#include <cuda_runtime.h>
#include <cuda_bf16.h>
#include <math.h>
#include <stdint.h>

#define B_    4
#define NTOK  4096
#define C_    256
#define H_    64
#define W_    64
#define NH2   4
#define N1_   1024

#define OUT_MAIN (B_*NTOK*C_)
#define OUT_M1   (OUT_MAIN)
#define OUT_M2   (OUT_MAIN + B_*NTOK)

// fp32 intermediates
static __device__ float d_proj[B_*NTOK*768];   // [q1|q2|kv2|lepe]
static __device__ float d_xsraw[4*B_*N1_*C_];  // 4 split-K partials
static __device__ float d_kv1[B_*N1_*C_];
static __device__ float d_cat[B_*NTOK*C_];
static __device__ float d_g[B_*N1_];
static __device__ float d_lm[B_*NTOK];
static __device__ float d_bcat[768];

// bf16 split buffers
static __device__ __nv_bfloat16 d_xh[B_*NTOK*C_],   d_xl[B_*NTOK*C_];
static __device__ __nv_bfloat16 d_wcath[256*768],   d_wcatl[256*768];
static __device__ __nv_bfloat16 d_w2h[131072],      d_w2l[131072];   // kv1 | proj
static __device__ __nv_bfloat16 d_srwh[1024*C_],    d_srwl[1024*C_];
static __device__ __nv_bfloat16 d_agh[4096*1024],   d_agl[4096*1024];
static __device__ __nv_bfloat16 d_xsh[B_*N1_*C_],   d_xsl[B_*N1_*C_];
static __device__ __nv_bfloat16 d_cath[B_*NTOK*C_], d_catl[B_*NTOK*C_];
static __device__ __nv_bfloat16 d_kv1h[B_*N1_*C_],  d_kv1l[B_*N1_*C_];

__device__ __constant__ float ATT_SCALE = 0.17677669529663687f; // 1/sqrt(32)

#define MMA_BF16(c, a, b) \
  asm volatile("mma.sync.aligned.m16n8k16.row.col.f32.bf16.bf16.f32 " \
    "{%0,%1,%2,%3}, {%4,%5,%6,%7}, {%8,%9}, {%0,%1,%2,%3};" \
    : "+f"((c)[0]), "+f"((c)[1]), "+f"((c)[2]), "+f"((c)[3]) \
    : "r"((a)[0]), "r"((a)[1]), "r"((a)[2]), "r"((a)[3]), \
      "r"((b)[0]), "r"((b)[1]))

#define LDSM_X4(r, addr) \
  asm volatile("ldmatrix.sync.aligned.m8n8.x4.shared.b16 {%0,%1,%2,%3}, [%4];" \
    : "=r"((r)[0]), "=r"((r)[1]), "=r"((r)[2]), "=r"((r)[3]) : "r"(addr))

#define LDSM_X4T(r, addr) \
  asm volatile("ldmatrix.sync.aligned.m8n8.x4.trans.shared.b16 {%0,%1,%2,%3}, [%4];" \
    : "=r"((r)[0]), "=r"((r)[1]), "=r"((r)[2]), "=r"((r)[3]) : "r"(addr))

#define BAR_PAIR(id) \
  asm volatile("bar.sync %0, 64;" :: "r"(id) : "memory")

__device__ __forceinline__ void cpa16(uint32_t saddr, const void* g) {
    asm volatile("cp.async.ca.shared.global [%0], [%1], 16;"
                 :: "r"(saddr), "l"(g));
}

// ---------------------------------------------------------------------------
// gemm2 (unchanged): bf16-split GEMM, 128x128, ldmatrix, cp.async.
// ---------------------------------------------------------------------------
#define GEMM2_SMEM 75776
__global__ void __launch_bounds__(256, 2) gemm2(
    const __nv_bfloat16* __restrict__ Ah, const __nv_bfloat16* __restrict__ Al, int lda,
    const __nv_bfloat16* __restrict__ Bh, const __nv_bfloat16* __restrict__ Bl, int ldb,
    const float* __restrict__ bias, float* __restrict__ Cm, int ldc,
    size_t cstride, int K, float alpha)
{
    extern __shared__ uint16_t sm16[];
    uint32_t sb = (uint32_t)__cvta_generic_to_shared(sm16);
    const uint32_t AHo = 0, ALo = 20480, BHo = 40960, BLo = 58368;

    int tid = threadIdx.x, lane = tid & 31, warp = tid >> 5;
    int wm = warp >> 2, wn = warp & 3;
    int m0 = blockIdx.y * 128, n0 = blockIdx.x * 128;
    int kz = blockIdx.z;
    int g = lane >> 2, t = lane & 3;

    const __nv_bfloat16* Ahp = Ah + (size_t)kz * K;
    const __nv_bfloat16* Alp = Al + (size_t)kz * K;
    const __nv_bfloat16* Bhp = Bh + (size_t)kz * K * ldb;
    const __nv_bfloat16* Blp = Bl + (size_t)kz * K * ldb;

    float acc[4][4][4];
#pragma unroll
    for (int i = 0; i < 4; i++)
#pragma unroll
        for (int j = 0; j < 4; j++)
#pragma unroll
            for (int c = 0; c < 4; c++) acc[i][j][c] = 0.f;

    int av = tid;
    int arow0 = av >> 2, aseg0 = av & 3;
    int arow1 = (av + 256) >> 2, aseg1 = (av + 256) & 3;
    int brow0 = av >> 4, bseg0 = av & 15;
    int brow1 = (av + 256) >> 4, bseg1 = (av + 256) & 15;

#define LOAD_CHUNK(bi, k0) do { \
    uint32_t aB = sb + (bi)*10240; \
    uint32_t bB = sb + (bi)*8704; \
    cpa16(aB + AHo + (uint32_t)((arow0*40 + aseg0*8)*2), Ahp + (size_t)(m0+arow0)*lda + (k0) + aseg0*8); \
    cpa16(aB + AHo + (uint32_t)((arow1*40 + aseg1*8)*2), Ahp + (size_t)(m0+arow1)*lda + (k0) + aseg1*8); \
    cpa16(aB + ALo + (uint32_t)((arow0*40 + aseg0*8)*2), Alp + (size_t)(m0+arow0)*lda + (k0) + aseg0*8); \
    cpa16(aB + ALo + (uint32_t)((arow1*40 + aseg1*8)*2), Alp + (size_t)(m0+arow1)*lda + (k0) + aseg1*8); \
    cpa16(bB + BHo + (uint32_t)((brow0*136 + bseg0*8)*2), Bhp + (size_t)((k0)+brow0)*ldb + n0 + bseg0*8); \
    cpa16(bB + BHo + (uint32_t)((brow1*136 + bseg1*8)*2), Bhp + (size_t)((k0)+brow1)*ldb + n0 + bseg1*8); \
    cpa16(bB + BLo + (uint32_t)((brow0*136 + bseg0*8)*2), Blp + (size_t)((k0)+brow0)*ldb + n0 + bseg0*8); \
    cpa16(bB + BLo + (uint32_t)((brow1*136 + bseg1*8)*2), Blp + (size_t)((k0)+brow1)*ldb + n0 + bseg1*8); \
    asm volatile("cp.async.commit_group;" ::: "memory"); \
} while (0)

    LOAD_CHUNK(0, 0);

    uint32_t aoff = (uint32_t)(((wm*64 + (lane & 15))*40 + (lane >> 4)*8) * 2);
    uint32_t boff = (uint32_t)(((lane & 15)*136 + wn*32 + (lane >> 4)*8) * 2);

    int nch = K >> 5;
    for (int c = 0; c < nch; c++) {
        int bi = c & 1;
        if (c + 1 < nch) {
            LOAD_CHUNK(bi ^ 1, (c + 1) << 5);
            asm volatile("cp.async.wait_group 1;" ::: "memory");
        } else {
            asm volatile("cp.async.wait_group 0;" ::: "memory");
        }
        __syncthreads();

        uint32_t aH = sb + AHo + bi*10240 + aoff;
        uint32_t aL = sb + ALo + bi*10240 + aoff;
        uint32_t bH = sb + BHo + bi*8704 + boff;
        uint32_t bL = sb + BLo + bi*8704 + boff;
#pragma unroll
        for (int kk = 0; kk < 32; kk += 16) {
            uint32_t bfh[4][2], bfl[4][2];
#pragma unroll
            for (int jj = 0; jj < 2; jj++) {
                uint32_t r[4];
                LDSM_X4T(r, bH + kk*272 + jj*32);
                bfh[2*jj][0] = r[0]; bfh[2*jj][1] = r[1];
                bfh[2*jj+1][0] = r[2]; bfh[2*jj+1][1] = r[3];
                LDSM_X4T(r, bL + kk*272 + jj*32);
                bfl[2*jj][0] = r[0]; bfl[2*jj][1] = r[1];
                bfl[2*jj+1][0] = r[2]; bfl[2*jj+1][1] = r[3];
            }
#pragma unroll
            for (int mt = 0; mt < 4; mt++) {
                uint32_t afh[4], afl[4];
                LDSM_X4(afh, aH + mt*1280 + kk*2);
                LDSM_X4(afl, aL + mt*1280 + kk*2);
#pragma unroll
                for (int nj = 0; nj < 4; nj++) {
                    MMA_BF16(acc[mt][nj], afh, bfh[nj]);
                    MMA_BF16(acc[mt][nj], afl, bfh[nj]);
                    MMA_BF16(acc[mt][nj], afh, bfl[nj]);
                }
            }
        }
        __syncthreads();
    }

    float* Co = Cm + (size_t)kz * cstride;
    if (bias) {
#pragma unroll
        for (int mt = 0; mt < 4; mt++)
#pragma unroll
            for (int nj = 0; nj < 4; nj++) {
                int row = m0 + wm*64 + mt*16 + g;
                int col = n0 + wn*32 + nj*8 + t*2;
                float b0 = bias[col], b1 = bias[col+1];
                *(float2*)(Co + (size_t)row*ldc + col) =
                    make_float2(alpha*(acc[mt][nj][0]+b0), alpha*(acc[mt][nj][1]+b1));
                *(float2*)(Co + (size_t)(row+8)*ldc + col) =
                    make_float2(alpha*(acc[mt][nj][2]+b0), alpha*(acc[mt][nj][3]+b1));
            }
    } else {
#pragma unroll
        for (int mt = 0; mt < 4; mt++)
#pragma unroll
            for (int nj = 0; nj < 4; nj++) {
                int row = m0 + wm*64 + mt*16 + g;
                int col = n0 + wn*32 + nj*8 + t*2;
                *(float2*)(Co + (size_t)row*ldc + col) =
                    make_float2(acc[mt][nj][0], acc[mt][nj][1]);
                *(float2*)(Co + (size_t)(row+8)*ldc + col) =
                    make_float2(acc[mt][nj][2], acc[mt][nj][3]);
            }
    }
#undef LOAD_CHUNK
}

// ---------------------------------------------------------------------------
// prep_all (unchanged). Grid 10512.
// ---------------------------------------------------------------------------
__global__ void prep_all(
    const float* __restrict__ x,
    const float* __restrict__ q1w, const float* __restrict__ q2w,
    const float* __restrict__ kv2w, const float* __restrict__ lepw,
    const float* __restrict__ q1b, const float* __restrict__ q2b,
    const float* __restrict__ kv2b, const float* __restrict__ lepb,
    const float* __restrict__ kv1w, const float* __restrict__ projw,
    const float* __restrict__ srw)
{
    int blk = blockIdx.x, tid = threadIdx.x;
    if (blk < 4096) {
        int i = blk * 256 + tid;
        float4 v = ((const float4*)x)[i];
        __nv_bfloat16 h0 = __float2bfloat16(v.x), h1 = __float2bfloat16(v.y);
        __nv_bfloat16 h2 = __float2bfloat16(v.z), h3 = __float2bfloat16(v.w);
        __nv_bfloat16 l0 = __float2bfloat16(v.x - __bfloat162float(h0));
        __nv_bfloat16 l1 = __float2bfloat16(v.y - __bfloat162float(h1));
        __nv_bfloat16 l2 = __float2bfloat16(v.z - __bfloat162float(h2));
        __nv_bfloat16 l3 = __float2bfloat16(v.w - __bfloat162float(h3));
        ((__nv_bfloat162*)d_xh)[i*2]   = __nv_bfloat162(h0, h1);
        ((__nv_bfloat162*)d_xh)[i*2+1] = __nv_bfloat162(h2, h3);
        ((__nv_bfloat162*)d_xl)[i*2]   = __nv_bfloat162(l0, l1);
        ((__nv_bfloat162*)d_xl)[i*2+1] = __nv_bfloat162(l2, l3);
    } else if (blk < 8192) {
        int v = (blk - 4096) * 256 + tid;
        int r = v >> 8, col4 = v & 255;
        int k = col4 * 4;
        int dd = k >> 8, ci = k & 255;
        int b = r >> 10, p = r & 1023;
        int ii = p >> 5, jj = p & 31;
        int di = dd >> 1, dj = dd & 1;
        int n = (2*ii + di) * W_ + 2*jj + dj;
        float4 xv = *(const float4*)(x + (size_t)(b * NTOK + n) * C_ + ci);
        __nv_bfloat16 h0 = __float2bfloat16(xv.x), h1 = __float2bfloat16(xv.y);
        __nv_bfloat16 h2 = __float2bfloat16(xv.z), h3 = __float2bfloat16(xv.w);
        __nv_bfloat16 l0 = __float2bfloat16(xv.x - __bfloat162float(h0));
        __nv_bfloat16 l1 = __float2bfloat16(xv.y - __bfloat162float(h1));
        __nv_bfloat16 l2 = __float2bfloat16(xv.z - __bfloat162float(h2));
        __nv_bfloat16 l3 = __float2bfloat16(xv.w - __bfloat162float(h3));
        size_t o = ((size_t)r * 1024 + k) >> 1;
        ((__nv_bfloat162*)d_agh)[o]   = __nv_bfloat162(h0, h1);
        ((__nv_bfloat162*)d_agh)[o+1] = __nv_bfloat162(h2, h3);
        ((__nv_bfloat162*)d_agl)[o]   = __nv_bfloat162(l0, l1);
        ((__nv_bfloat162*)d_agl)[o+1] = __nv_bfloat162(l2, l3);
    } else if (blk < 8960) {
        int idx = (blk - 8192) * 256 + tid;
        int k = idx / 768, col = idx - k * 768;
        float v;
        if (col < 128)       v = q1w[k*128 + col];
        else if (col < 256)  v = q2w[k*128 + col - 128];
        else if (col < 512)  v = kv2w[k*256 + col - 256];
        else                 v = lepw[k*256 + col - 512];
        __nv_bfloat16 h = __float2bfloat16(v);
        d_wcath[idx] = h;
        d_wcatl[idx] = __float2bfloat16(v - __bfloat162float(h));
        if (idx < 768) {
            float b = (idx < 128) ? q1b[idx] : (idx < 256) ? q2b[idx-128]
                    : (idx < 512) ? kv2b[idx-256] : lepb[idx-512];
            d_bcat[idx] = b;
        }
    } else if (blk < 10496) {
        int idx = (blk - 8960) * 256 + tid;
        float v;
        if (idx < 65536) {
            v = kv1w[idx];
            __nv_bfloat16 h = __float2bfloat16(v);
            d_w2h[idx] = h; d_w2l[idx] = __float2bfloat16(v - __bfloat162float(h));
        } else if (idx < 131072) {
            v = projw[idx - 65536];
            __nv_bfloat16 h = __float2bfloat16(v);
            d_w2h[idx] = h; d_w2l[idx] = __float2bfloat16(v - __bfloat162float(h));
        } else {
            int i = idx - 131072;
            int co = i & 255, kk = i >> 8;
            int dd = kk >> 8, ci = kk & 255;
            v = srw[co * 1024 + ci * 4 + dd];
            __nv_bfloat16 h = __float2bfloat16(v);
            d_srwh[i] = h; d_srwl[i] = __float2bfloat16(v - __bfloat162float(h));
        }
    } else {
        int i = (blk - 10496) * 256 + tid;
        if (i < B_ * N1_) d_g[i] = 0.f;
    }
}

// ---------------------------------------------------------------------------
__global__ void ln_gelu_kernel(const float* __restrict__ nw,
                               const float* __restrict__ nb,
                               const float* __restrict__ srb)
{
    __shared__ float sh[8];
    int r = blockIdx.x, c = threadIdx.x;
    size_t o = (size_t)r * C_ + c;
    const size_t P = (size_t)B_ * N1_ * C_;
    float v = d_xsraw[o] + d_xsraw[o + P] + d_xsraw[o + 2*P] + d_xsraw[o + 3*P]
            + srb[c];

    float s = v;
#pragma unroll
    for (int o2 = 16; o2 > 0; o2 >>= 1) s += __shfl_xor_sync(0xffffffffu, s, o2);
    if ((c & 31) == 0) sh[c >> 5] = s;
    __syncthreads();
    if (c < 32) {
        float t = (c < 8) ? sh[c] : 0.f;
#pragma unroll
        for (int o2 = 4; o2 > 0; o2 >>= 1) t += __shfl_xor_sync(0xffffffffu, t, o2);
        if (c == 0) sh[0] = t;
    }
    __syncthreads();
    float mean = sh[0] * (1.f / 256.f);
    __syncthreads();

    float dv = v - mean;
    float q = dv * dv;
#pragma unroll
    for (int o2 = 16; o2 > 0; o2 >>= 1) q += __shfl_xor_sync(0xffffffffu, q, o2);
    if ((c & 31) == 0) sh[c >> 5] = q;
    __syncthreads();
    if (c < 32) {
        float t = (c < 8) ? sh[c] : 0.f;
#pragma unroll
        for (int o2 = 4; o2 > 0; o2 >>= 1) t += __shfl_xor_sync(0xffffffffu, t, o2);
        if (c == 0) sh[0] = t;
    }
    __syncthreads();
    float var = sh[0] * (1.f / 256.f);

    float y = dv * rsqrtf(var + 1e-5f) * nw[c] + nb[c];
    float ge = 0.5f * y * (1.f + erff(y * 0.70710678118654752f));
    __nv_bfloat16 h = __float2bfloat16(ge);
    d_xsh[o] = h;
    d_xsl[o] = __float2bfloat16(ge - __bfloat162float(h));
}

// ---------------------------------------------------------------------------
__global__ void kv1split()
{
    int i = blockIdx.x * 256 + threadIdx.x;
    float4 v = ((const float4*)d_kv1)[i];
    __nv_bfloat16 h0 = __float2bfloat16(v.x), h1 = __float2bfloat16(v.y);
    __nv_bfloat16 h2 = __float2bfloat16(v.z), h3 = __float2bfloat16(v.w);
    __nv_bfloat16 l0 = __float2bfloat16(v.x - __bfloat162float(h0));
    __nv_bfloat16 l1 = __float2bfloat16(v.y - __bfloat162float(h1));
    __nv_bfloat16 l2 = __float2bfloat16(v.z - __bfloat162float(h2));
    __nv_bfloat16 l3 = __float2bfloat16(v.w - __bfloat162float(h3));
    ((__nv_bfloat162*)d_kv1h)[i*2]   = __nv_bfloat162(h0, h1);
    ((__nv_bfloat162*)d_kv1h)[i*2+1] = __nv_bfloat162(h2, h3);
    ((__nv_bfloat162*)d_kv1l)[i*2]   = __nv_bfloat162(l0, l1);
    ((__nv_bfloat162*)d_kv1l)[i*2+1] = __nv_bfloat162(l2, l3);
}

// ---------------------------------------------------------------------------
// attn1_mma: tensor-core branch-1 attention, 16 q/block, 2 CTAs/SM,
// minimized barrier scope: QK per-warp, AV per-pair (named barriers).
// ---------------------------------------------------------------------------
#define ATTN_SMEM 93248
__global__ void __launch_bounds__(256) attn1_mma(
    const float* __restrict__ proj,
    const __nv_bfloat16* __restrict__ kvh,
    const __nv_bfloat16* __restrict__ kvl,
    float* __restrict__ cat, float* __restrict__ g)
{
    extern __shared__ char smc[];
    float* S = (float*)smc;                              // 65536
    __nv_bfloat16* Qh = (__nv_bfloat16*)(smc + 65536);   // 1280
    __nv_bfloat16* Ql = (__nv_bfloat16*)(smc + 66816);   // 1280
    float* inv = (float*)(smc + 68096);                  // 64
    __nv_bfloat16* Ph = (__nv_bfloat16*)(smc + 88640);   // 2304
    __nv_bfloat16* Pl = (__nv_bfloat16*)(smc + 90944);   // 2304
    uint32_t sb  = (uint32_t)__cvta_generic_to_shared(smc);
    uint32_t ktb = sb + 68160;                           // KV tiles, 20480B
    uint32_t qhb = sb + 65536, qlb = sb + 66816;
    uint32_t phb = sb + 88640, plb = sb + 90944;

    int tid = threadIdx.x, lane = tid & 31, warp = tid >> 5;
    int bh = blockIdx.y, b = bh >> 2, h = bh & 3;
    int q0 = blockIdx.x * 16;
    int gq = lane >> 2, tl = lane & 3;

    const float* Qg = proj + (size_t)(b * NTOK + q0) * 768 + h * 32;
    const __nv_bfloat16* Kh = kvh + (size_t)b * N1_ * 256 + h * 32;
    const __nv_bfloat16* Kl = kvl + (size_t)b * N1_ * 256 + h * 32;

    // ---- Q load + scale + split (threads 0-127) ----
    if (tid < 128) {
        int q = tid >> 3, dg = (tid & 7) * 4;
        float4 v = *(const float4*)(Qg + (size_t)q * 768 + dg);
        float sc = ATT_SCALE;
        float a0 = v.x*sc, a1 = v.y*sc, a2 = v.z*sc, a3 = v.w*sc;
        __nv_bfloat16 h0 = __float2bfloat16(a0), h1 = __float2bfloat16(a1);
        __nv_bfloat16 h2 = __float2bfloat16(a2), h3 = __float2bfloat16(a3);
        Qh[q*40+dg+0] = h0; Qh[q*40+dg+1] = h1;
        Qh[q*40+dg+2] = h2; Qh[q*40+dg+3] = h3;
        Ql[q*40+dg+0] = __float2bfloat16(a0 - __bfloat162float(h0));
        Ql[q*40+dg+1] = __float2bfloat16(a1 - __bfloat162float(h1));
        Ql[q*40+dg+2] = __float2bfloat16(a2 - __bfloat162float(h2));
        Ql[q*40+dg+3] = __float2bfloat16(a3 - __bfloat162float(h3));
    }
    int lkey = tid >> 2, lseg = tid & 3;
    int wk2 = warp >> 1, wd = warp & 1;
    int pl  = ((warp & 1) << 5) | lane;          // lane within pair, 0..63

    // K tile load: warp-private rows [8w, 8w+8)
#define LOAD_K(t_, buf_) do { \
    cpa16(ktb + (buf_)*10240 + (uint32_t)((lkey*40 + lseg*8)*2), \
          Kh + (size_t)((t_)*64 + lkey)*256 + lseg*8); \
    cpa16(ktb + (buf_)*10240 + 5120 + (uint32_t)((lkey*40 + lseg*8)*2), \
          Kl + (size_t)((t_)*64 + lkey)*256 + lseg*8); \
    asm volatile("cp.async.commit_group;" ::: "memory"); \
} while (0)
    // V tile load: pair-private rows [16*wk2, +16), 2 items/lane
#define LOAD_V(t_, buf_) do { \
    _Pragma("unroll") \
    for (int it_ = 0; it_ < 2; it_++) { \
        int i_ = pl + it_*64; \
        int pln_ = i_ >> 6; \
        int rr_ = (i_ >> 2) & 15; \
        int sg_ = i_ & 3; \
        cpa16(ktb + (buf_)*10240 + pln_*5120 + \
              (uint32_t)(((wk2*16 + rr_)*40 + sg_*8)*2), \
              (pln_ ? Kl : Kh) + (size_t)((t_)*64 + wk2*16 + rr_)*256 + 128 + sg_*8); \
    } \
    asm volatile("cp.async.commit_group;" ::: "memory"); \
} while (0)

    LOAD_K(0, 0);
    __syncthreads();   // Q in smem (block: Q is cross-warp)

    // Q fragments (persistent)
    uint32_t qfh[2][4], qfl[2][4];
#pragma unroll
    for (int ks = 0; ks < 2; ks++) {
        uint32_t off = (uint32_t)((((lane&15))*40 + ks*16 + (lane>>4)*8)*2);
        LDSM_X4(qfh[ks], qhb + off);
        LDSM_X4(qfl[ks], qlb + off);
    }

    // ---- QK loop: warp-private K rows + S cols -> no block syncs ----
    for (int t = 0; t < 16; t++) {
        int bi = t & 1;
        if (t < 15) {
            LOAD_K(t+1, bi^1);
            asm volatile("cp.async.wait_group 1;" ::: "memory");
        } else {
            asm volatile("cp.async.wait_group 0;" ::: "memory");
        }
        __syncwarp();

        uint32_t kb = ktb + bi*10240 +
                      (uint32_t)(((warp*8 + (lane&7))*40 + (lane>>3)*8)*2);
        uint32_t rh[4], rl[4];
        LDSM_X4(rh, kb);
        LDSM_X4(rl, kb + 5120);

        float acc[4];
#pragma unroll
        for (int j = 0; j < 4; j++) acc[j] = 0.f;
#pragma unroll
        for (int ks = 0; ks < 2; ks++) {
            MMA_BF16(acc, qfh[ks], (&rh[2*ks]));
            MMA_BF16(acc, qfl[ks], (&rh[2*ks]));
            MMA_BF16(acc, qfh[ks], (&rl[2*ks]));
        }
        int kb0 = t*64 + warp*8 + tl*2;
        *(float2*)&S[(size_t)gq*1024 + kb0]     = make_float2(acc[0], acc[1]);
        *(float2*)&S[(size_t)(gq+8)*1024 + kb0] = make_float2(acc[2], acc[3]);
    }
    __syncthreads();   // S complete + all K reads done

    LOAD_V(0, 0);      // overlaps softmax (pair-private V rows)

    // ---- softmax: 16 rows, 2 per warp ----
    {
#pragma unroll
        for (int rr = 0; rr < 2; rr++) {
            int row = warp * 2 + rr;
            float* Sr = S + (size_t)row * 1024;
            float m = -1e30f;
#pragma unroll
            for (int i = 0; i < 32; i++) m = fmaxf(m, Sr[lane + 32*i]);
#pragma unroll
            for (int o = 16; o > 0; o >>= 1)
                m = fmaxf(m, __shfl_xor_sync(0xffffffffu, m, o));
            float s = 0.f;
#pragma unroll
            for (int i = 0; i < 32; i++) {
                float e = __expf(Sr[lane + 32*i] - m);
                Sr[lane + 32*i] = e;
                s += e;
            }
#pragma unroll
            for (int o = 16; o > 0; o >>= 1)
                s += __shfl_xor_sync(0xffffffffu, s, o);
            if (lane == 0) inv[row] = 1.f / s;
        }
    }
    __syncthreads();

    // ---- column sums -> g ----
    {
        float a0 = 0.f, a1 = 0.f, a2 = 0.f, a3 = 0.f;
#pragma unroll
        for (int q = 0; q < 16; q++) {
            float iv = inv[q];
            const float* Sq = S + (size_t)q * 1024;
            a0 += Sq[tid      ] * iv;
            a1 += Sq[tid + 256] * iv;
            a2 += Sq[tid + 512] * iv;
            a3 += Sq[tid + 768] * iv;
        }
        float* gb = g + b * N1_;
        atomicAdd(&gb[tid      ], a0);
        atomicAdd(&gb[tid + 256], a1);
        atomicAdd(&gb[tid + 512], a2);
        atomicAdd(&gb[tid + 768], a3);
    }

    // ---- AV loop: pair-scoped barriers only ----
    int barid = 1 + wk2;
    float av[2][4];
#pragma unroll
    for (int j = 0; j < 2; j++)
#pragma unroll
        for (int c = 0; c < 4; c++) av[j][c] = 0.f;

    for (int t = 0; t < 16; t++) {
        int bi = t & 1;
        if (t < 15) LOAD_V(t+1, bi^1);
        // convert pair's P block (16 rows x 16 cols at wk2*16), 4 elems/lane
#pragma unroll
        for (int e = 0; e < 4; e++) {
            int ii = pl*4 + e;
            int q = ii >> 4, k = wk2*16 + (ii & 15);
            float val = S[(size_t)q*1024 + t*64 + k];
            __nv_bfloat16 hh = __float2bfloat16(val);
            Ph[q*72 + k] = hh;
            Pl[q*72 + k] = __float2bfloat16(val - __bfloat162float(hh));
        }
        if (t < 15) asm volatile("cp.async.wait_group 1;" ::: "memory");
        else        asm volatile("cp.async.wait_group 0;" ::: "memory");
        BAR_PAIR(barid);   // P writes + V data visible pair-wide

        uint32_t poff = (uint32_t)((((lane&15))*72 + wk2*16 + (lane>>4)*8)*2);
        uint32_t pah[4], pal[4];
        LDSM_X4(pah, phb + poff);
        LDSM_X4(pal, plb + poff);
        uint32_t vb = ktb + bi*10240 +
            (uint32_t)(((wk2*16 + (lane&15))*40 + wd*16 + (lane>>4)*8)*2);
        uint32_t vh4[4], vl4[4];
        LDSM_X4T(vh4, vb);
        LDSM_X4T(vl4, vb + 5120);
#pragma unroll
        for (int j = 0; j < 2; j++) {
            MMA_BF16(av[j], pah, (&vh4[2*j]));
            MMA_BF16(av[j], pah, (&vl4[2*j]));
            MMA_BF16(av[j], pal, (&vh4[2*j]));
        }
        BAR_PAIR(barid);   // reads done before next-iter conversion/load
    }
    __syncthreads();       // all AV reads of S done before reduce reuses S

    // ---- reduce 4 k-quarters (S region reused) ----
    float* red = (float*)smc;
    if (wk2 > 0) {
        float* d = red + (size_t)((((wk2-1)*2 + wd)*32) + lane)*8;
        d[0] = av[0][0]; d[1] = av[0][1]; d[2] = av[0][2]; d[3] = av[0][3];
        d[4] = av[1][0]; d[5] = av[1][1]; d[6] = av[1][2]; d[7] = av[1][3];
    }
    __syncthreads();
    if (wk2 == 0) {
#pragma unroll
        for (int pp = 0; pp < 3; pp++) {
            const float* s = red + (size_t)(((pp*2 + wd)*32) + lane)*8;
            av[0][0] += s[0]; av[0][1] += s[1]; av[0][2] += s[2]; av[0][3] += s[3];
            av[1][0] += s[4]; av[1][1] += s[5]; av[1][2] += s[6]; av[1][3] += s[7];
        }
        float i0 = inv[gq], i1 = inv[gq + 8];
        size_t r0 = (size_t)(b*NTOK + q0 + gq) * 256;
#pragma unroll
        for (int j = 0; j < 2; j++) {
            int col = h*32 + wd*16 + j*8 + tl*2;
            *(float2*)&cat[r0 + col] = make_float2(av[j][0]*i0, av[j][1]*i0);
            *(float2*)&cat[r0 + 8*256 + col] = make_float2(av[j][2]*i1, av[j][3]*i1);
        }
    }
#undef LOAD_K
#undef LOAD_V
}

// ---------------------------------------------------------------------------
__global__ void attn2_kernel(const float* __restrict__ proj)
{
    int win = blockIdx.x;
    int b = win >> 8, rem = win & 255, gy = rem >> 4, gx = rem & 15;
    int tid = threadIdx.x, h = tid >> 5, lane = tid & 31;

    __shared__ float Qs[4][16][32];
    __shared__ float Ks[4][16][32];
    __shared__ float Vs[4][16][32];
    __shared__ float csum[16];

    for (int i = lane; i < 16 * 32; i += 32) {
        int t = i >> 5, dd = i & 31;
        int n = (gy * 4 + (t >> 2)) * W_ + gx * 4 + (t & 3);
        const float* base = proj + (size_t)(b * NTOK + n) * 768;
        Qs[h][t][dd] = base[128 + h * 32 + dd];
        Ks[h][t][dd] = base[256 + h * 32 + dd];
        Vs[h][t][dd] = base[256 + 128 + h * 32 + dd];
    }
    if (tid < 16) csum[tid] = 0.f;
    __syncthreads();

    if (lane < 16) {
        int q = lane;
        float s[16];
        float mx = -1e30f;
#pragma unroll
        for (int m = 0; m < 16; m++) {
            float dot = 0.f;
#pragma unroll
            for (int dd = 0; dd < 32; dd++) dot += Qs[h][q][dd] * Ks[h][m][dd];
            s[m] = dot * ATT_SCALE;
            mx = fmaxf(mx, s[m]);
        }
        float sum = 0.f;
#pragma unroll
        for (int m = 0; m < 16; m++) { s[m] = __expf(s[m] - mx); sum += s[m]; }
        float iv = 1.f / sum;
#pragma unroll
        for (int m = 0; m < 16; m++) {
            s[m] *= iv;
            atomicAdd(&csum[m], s[m]);
        }
        int nq = (gy * 4 + (q >> 2)) * W_ + gx * 4 + (q & 3);
        float* outp = d_cat + (size_t)(b * NTOK + nq) * 256 + 128 + h * 32;
#pragma unroll
        for (int dd = 0; dd < 32; dd++) {
            float o = 0.f;
#pragma unroll
            for (int m = 0; m < 16; m++) o += s[m] * Vs[h][m][dd];
            outp[dd] = o;
        }
    }
    __syncthreads();
    if (tid < 16) {
        int m = tid;
        int np = (gy * 4 + (m >> 2)) * W_ + gx * 4 + (m & 3);
        d_lm[b * NTOK + np] = csum[m] * (1.f / 64.f);
    }
}

// ---------------------------------------------------------------------------
__global__ void lepe_add_kernel(const float* __restrict__ proj,
                                const float* __restrict__ w9,
                                const float* __restrict__ cb)
{
    int r = blockIdx.x;
    int c = threadIdx.x;
    int b = r >> 12, n = r & 4095, y = n >> 6, x = n & 63;
    float wv[9];
#pragma unroll
    for (int t = 0; t < 9; t++) wv[t] = w9[c * 9 + t];
    float acc = cb[c];
#pragma unroll
    for (int dy = 0; dy < 3; dy++) {
        int yy = y + dy - 1;
        if (yy < 0 || yy >= H_) continue;
#pragma unroll
        for (int dx = 0; dx < 3; dx++) {
            int xx = x + dx - 1;
            if (xx < 0 || xx >= W_) continue;
            acc += wv[dy * 3 + dx] *
                   proj[(size_t)(b * NTOK + yy * W_ + xx) * 768 + 512 + c];
        }
    }
    float v = d_cat[(size_t)r * C_ + c] + acc;
    __nv_bfloat16 h = __float2bfloat16(v);
    d_cath[(size_t)r * C_ + c] = h;
    d_catl[(size_t)r * C_ + c] = __float2bfloat16(v - __bfloat162float(h));
}

// ---------------------------------------------------------------------------
__global__ void mask_kernel(float* __restrict__ out)
{
    int idx = blockIdx.x * 256 + threadIdx.x;
    int b = idx >> 12, pos = idx & 4095, y = pos >> 6, x = pos & 63;
    float gv = d_g[b * N1_ + (y >> 1) * 32 + (x >> 1)] * (1.f / (NH2 * NTOK));
    float val = d_lm[idx] + gv;
    out[OUT_M1 + idx] = val;
    out[OUT_M2 + b * NTOK + x * 64 + y] = val;
}

// ---------------------------------------------------------------------------
extern "C" void kernel_launch(void* const* d_in, const int* in_sizes, int n_in,
                              void* d_out, int out_size)
{
    const float* x      = (const float*)d_in[0];
    const float* q1_w   = (const float*)d_in[1];
    const float* q1_b   = (const float*)d_in[2];
    const float* kv1_w  = (const float*)d_in[3];
    const float* kv1_b  = (const float*)d_in[4];
    const float* q2_w   = (const float*)d_in[5];
    const float* q2_b   = (const float*)d_in[6];
    const float* kv2_w  = (const float*)d_in[7];
    const float* kv2_b  = (const float*)d_in[8];
    const float* lepe_w = (const float*)d_in[9];
    const float* lepe_b = (const float*)d_in[10];
    const float* lcw    = (const float*)d_in[11];
    const float* lcb    = (const float*)d_in[12];
    const float* sr_w   = (const float*)d_in[13];
    const float* sr_b   = (const float*)d_in[14];
    const float* nw     = (const float*)d_in[15];
    const float* nb     = (const float*)d_in[16];
    const float* pw     = (const float*)d_in[17];
    const float* pb     = (const float*)d_in[18];
    float* out = (float*)d_out;

    void* p;
    float *projp, *kv1p, *catp, *gp, *xsraw, *bcat;
    __nv_bfloat16 *xh, *xl, *wcath, *wcatl, *w2h, *w2l, *srwh, *srwl;
    __nv_bfloat16 *agh, *agl, *xsh, *xsl, *cath, *catl, *kv1h, *kv1l;
    cudaGetSymbolAddress(&p, d_proj);  projp = (float*)p;
    cudaGetSymbolAddress(&p, d_kv1);   kv1p  = (float*)p;
    cudaGetSymbolAddress(&p, d_cat);   catp  = (float*)p;
    cudaGetSymbolAddress(&p, d_g);     gp    = (float*)p;
    cudaGetSymbolAddress(&p, d_xsraw); xsraw = (float*)p;
    cudaGetSymbolAddress(&p, d_bcat);  bcat  = (float*)p;
    cudaGetSymbolAddress(&p, d_xh);    xh    = (__nv_bfloat16*)p;
    cudaGetSymbolAddress(&p, d_xl);    xl    = (__nv_bfloat16*)p;
    cudaGetSymbolAddress(&p, d_wcath); wcath = (__nv_bfloat16*)p;
    cudaGetSymbolAddress(&p, d_wcatl); wcatl = (__nv_bfloat16*)p;
    cudaGetSymbolAddress(&p, d_w2h);   w2h   = (__nv_bfloat16*)p;
    cudaGetSymbolAddress(&p, d_w2l);   w2l   = (__nv_bfloat16*)p;
    cudaGetSymbolAddress(&p, d_srwh);  srwh  = (__nv_bfloat16*)p;
    cudaGetSymbolAddress(&p, d_srwl);  srwl  = (__nv_bfloat16*)p;
    cudaGetSymbolAddress(&p, d_agh);   agh   = (__nv_bfloat16*)p;
    cudaGetSymbolAddress(&p, d_agl);   agl   = (__nv_bfloat16*)p;
    cudaGetSymbolAddress(&p, d_xsh);   xsh   = (__nv_bfloat16*)p;
    cudaGetSymbolAddress(&p, d_xsl);   xsl   = (__nv_bfloat16*)p;
    cudaGetSymbolAddress(&p, d_cath);  cath  = (__nv_bfloat16*)p;
    cudaGetSymbolAddress(&p, d_catl);  catl  = (__nv_bfloat16*)p;
    cudaGetSymbolAddress(&p, d_kv1h);  kv1h  = (__nv_bfloat16*)p;
    cudaGetSymbolAddress(&p, d_kv1l);  kv1l  = (__nv_bfloat16*)p;

    cudaFuncSetAttribute(attn1_mma,
                         cudaFuncAttributeMaxDynamicSharedMemorySize, ATTN_SMEM);
    cudaFuncSetAttribute(gemm2,
                         cudaFuncAttributeMaxDynamicSharedMemorySize, GEMM2_SMEM);

    const size_t XS_STRIDE = (size_t)B_ * N1_ * C_;

    // 1: all prep
    prep_all<<<10512, 256>>>(x, q1_w, q2_w, kv2_w, lepe_w,
                             q1_b, q2_b, kv2_b, lepe_b, kv1_w, pw, sr_w);

    // 2: sr conv GEMM, split-K x4
    gemm2<<<dim3(2, 32, 4), 256, GEMM2_SMEM>>>(agh, agl, 1024, srwh, srwl, 256,
                                               (const float*)0, xsraw, 256,
                                               XS_STRIDE, 256, 1.f);
    // 3: LN+GELU
    ln_gelu_kernel<<<B_ * N1_, 256>>>(nw, nb, sr_b);

    // 4: fused x-projections (profiled)
    gemm2<<<dim3(6, 128, 1), 256, GEMM2_SMEM>>>(xh, xl, 256, wcath, wcatl, 768,
                                                bcat, projp, 768, 0, 256, 1.f);

    // 5: kv1 GEMM
    gemm2<<<dim3(2, 32, 1), 256, GEMM2_SMEM>>>(xsh, xsl, 256, w2h, w2l, 256,
                                               kv1_b, kv1p, 256, 0, 256, 1.f);
    // 6: kv1 -> bf16 split
    kv1split<<<1024, 256>>>();

    // 7: tensor-core branch-1 attention
    attn1_mma<<<dim3(256, 16), 256, ATTN_SMEM>>>(projp, kv1h, kv1l, catp, gp);

    // 8-9: branch 2 + lepe/cat split
    attn2_kernel<<<B_ * 16 * 16, 128>>>(projp);
    lepe_add_kernel<<<B_ * NTOK, 256>>>(projp, lcw, lcb);

    // 10: final projection
    gemm2<<<dim3(2, 128, 1), 256, GEMM2_SMEM>>>(cath, catl, 256,
                                                w2h + 65536, w2l + 65536, 256,
                                                pb, out, 256, 0, 256, 2.f);
    // 11: masks
    mask_kernel<<<64, 256>>>(out);
}